// round 4
// baseline (speedup 1.0000x reference)
#include <cuda_runtime.h>
#include <cstdint>

#define B_  512
#define T_  512
#define F_  128
#define NU  50
#define NC  150   // 3*NU
#define XP  160   // padded X row (floats)

// Scratch for projected inputs X[b][t][160] (cols 150..159 unused garbage).
__device__ float g_X[(size_t)B_ * T_ * XP];

typedef unsigned long long ull;

// ---------------- packed f32x2 helpers ----------------
__device__ __forceinline__ ull dup2(float x) {
    ull r;
    asm("mov.b64 %0, {%1, %1};" : "=l"(r) : "f"(x));
    return r;
}
__device__ __forceinline__ void fma2(ull& d, ull a, ull b) {
    asm("fma.rn.f32x2 %0, %1, %2, %0;" : "+l"(d) : "l"(a), "l"(b));
}
__device__ __forceinline__ void unpack2(ull v, float& lo, float& hi) {
    asm("mov.b64 {%0, %1}, %2;" : "=f"(lo), "=f"(hi) : "l"(v));
}

__device__ __forceinline__ float sigm(float x) {
    return __fdividef(1.f, 1.f + __expf(-x));
}
__device__ __forceinline__ float tanh_fast(float x) {
    return __fdividef(2.f, 1.f + __expf(-2.f * x)) - 1.f;
}

__device__ __forceinline__ uint32_t smem_u32(const void* p) {
    uint32_t a;
    asm("{ .reg .u64 t; cvta.to.shared.u64 t, %1; cvt.u32.u64 %0, t; }"
        : "=r"(a) : "l"(p));
    return a;
}

// ---------------- Kernel 1: input projection (unchanged from R3) ----------------
#define RT    128            // rows (timesteps) per tile
#define AS    129            // odd stride for transposed A (conflict-free STS)
#define SM_W  (F_ * XP)      // 20480 floats
#define SM_B  (XP)           // 160
#define SM_A  (F_ * AS)      // 16512
#define SMEM_XPROJ ((SM_W + SM_B + SM_A) * 4)   // ~148.6 KB

__global__ void __launch_bounds__(512, 1) xproj_kernel(
    const float* __restrict__ inp, const float* __restrict__ W,
    const float* __restrict__ bb, const float* __restrict__ dp)
{
    extern __shared__ float sm[];
    float* Weff = sm;              // [128][160]
    float* bi_s = sm + SM_W;       // [160]
    float* A_s  = bi_s + SM_B;     // [128][129]  (k-major, transposed tile)

    const int b   = blockIdx.x;
    const int tid = threadIdx.x;

    for (int idx = tid; idx < F_ * XP; idx += 512) {
        int k = idx / XP, c = idx - k * XP;
        float w = 0.f;
        if (c < NC) w = W[k * NC + c] * dp[(c / NU) * (B_ * F_) + b * F_ + k];
        Weff[idx] = w;
    }
    for (int c = tid; c < XP; c += 512)
        bi_s[c] = (c < NC) ? bb[c] : 0.f;

    const int cx = tid & 15;       // col-pair lane: pairs {j*16+cx, j<5}
    const int ry = tid >> 4;       // row group 0..31: rows ry*4 .. ry*4+3
    const int r0 = ry * 4;
    const ull* Wv = reinterpret_cast<const ull*>(Weff);
    const ull* bv = reinterpret_cast<const ull*>(bi_s);

    for (int tile = 0; tile < T_ / RT; ++tile) {
        const int t0 = tile * RT;
        __syncthreads();
        const float* src = inp + ((size_t)b * T_ + t0) * F_;
        for (int idx = tid; idx < RT * F_; idx += 512) {
            int r = idx >> 7, k = idx & 127;
            A_s[k * AS + r] = src[idx];
        }
        __syncthreads();

        ull acc[4][5];
        #pragma unroll
        for (int i = 0; i < 4; ++i)
            #pragma unroll
            for (int j = 0; j < 5; ++j)
                acc[i][j] = bv[j * 16 + cx];

        #pragma unroll 2
        for (int k = 0; k < F_; ++k) {
            ull w[5];
            #pragma unroll
            for (int j = 0; j < 5; ++j)
                w[j] = Wv[k * (XP / 2) + j * 16 + cx];
            #pragma unroll
            for (int i = 0; i < 4; ++i) {
                ull ad = dup2(A_s[k * AS + r0 + i]);
                #pragma unroll
                for (int j = 0; j < 5; ++j)
                    fma2(acc[i][j], ad, w[j]);
            }
        }

        #pragma unroll
        for (int i = 0; i < 4; ++i) {
            ull* Xr = reinterpret_cast<ull*>(g_X + ((size_t)b * T_ + t0 + r0 + i) * XP);
            #pragma unroll
            for (int j = 0; j < 5; ++j)
                Xr[j * 16 + cx] = acc[i][j];
        }
    }
}

// ---------------- Kernel 2: recurrent scan (shuffle-reduced, 1 bar/step) ----
// 128 CTAs x 4 rows, 256 threads. Thread (u = tid>>2, s = tid&3): j-split s
// over JSEG=13 j's, owns row s's h-state for unit u. Partial gate sums for all
// 4 rows (2x2 packed in f32x2) are butterfly-reduced across the 4 split lanes
// (adjacent lanes, shfl.bfly xor 1,2). hm is double-buffered -> ONE
// __syncthreads per step. X staged by cp.async double buffer (bank-padded).
#define JSEG 13
#define JPAD 52                       // 4*JSEG; j=50,51 stay zero
#define CH   8                        // steps per chunk
#define XQ   38                       // float4 per (row,step)
#define XROWF4 (CH * XQ + 2)          // +32B pad -> 8-bank offset per row
#define CHUNK_F4 (4 * CH * XQ)        // 1216

__global__ void __launch_bounds__(256, 1) scan_kernel(
    const float* __restrict__ U, const float* __restrict__ bb,
    const float* __restrict__ Wd, const float* __restrict__ bd,
    const float* __restrict__ rdp, float* __restrict__ out)
{
    __shared__ float4 hm[2][3][JPAD];      // [buf][gate][j] = {g_r0,g_r1,g_r2,g_r3}
    __shared__ float4 Xs[2 * 4 * XROWF4];  // [(buf*4+row)*XROWF4 + tt*XQ + q]
    __shared__ float  head[4][64];

    const int tid = threadIdx.x;
    const int u   = tid >> 2;             // unit 0..63 (active if < 50)
    const int s   = tid & 3;              // j-split AND owned row
    const int b0  = blockIdx.x * 4;
    const bool active = (u < NU);
    const int jbeg = s * JSEG;

    for (int idx = tid; idx < 2 * 3 * JPAD; idx += 256)
        (&hm[0][0][0])[idx] = make_float4(0.f, 0.f, 0.f, 0.f);

    // U slice in registers, duplicated for 2-row-packed fma2
    ull Uzd[JSEG], Urd[JSEG], Uhd[JSEG];
    #pragma unroll
    for (int jj = 0; jj < JSEG; ++jj) {
        int j = jbeg + jj;
        float vz = 0.f, vr = 0.f, vh = 0.f;
        if (active && j < NU) {
            vz = U[j * NC + u];
            vr = U[j * NC + NU + u];
            vh = U[j * NC + 2 * NU + u];
        }
        Uzd[jj] = dup2(vz); Urd[jj] = dup2(vr); Uhd[jj] = dup2(vh);
    }

    float br0 = 0.f, br1 = 0.f, br2 = 0.f, wdu = 0.f;
    float rdp0 = 0.f, rdp1 = 0.f, rdp2 = 0.f, h = 0.f;
    if (active) {
        br0 = bb[NC + u]; br1 = bb[NC + NU + u]; br2 = bb[NC + 2 * NU + u];
        wdu = Wd[u];
        rdp0 = rdp[0 * (B_ * NU) + (b0 + s) * NU + u];
        rdp1 = rdp[1 * (B_ * NU) + (b0 + s) * NU + u];
        rdp2 = rdp[2 * (B_ * NU) + (b0 + s) * NU + u];
    }

    // ---- cp.async chunk loader (all 256 threads) ----
    const uint32_t xs_base = smem_u32(&Xs[0]);
    auto issue_chunk = [&](int c, int buf) {
        #pragma unroll
        for (int it = 0; it < 5; ++it) {
            int lin = it * 256 + tid;
            if (lin < CHUNK_F4) {
                int r   = lin / (CH * XQ);
                int rem = lin - r * (CH * XQ);
                int tt  = rem / XQ;
                int q   = rem - tt * XQ;
                const float* g = g_X + ((size_t)(b0 + r) * T_ + c * CH + tt) * XP + q * 4;
                uint32_t dst = xs_base +
                    (uint32_t)((buf * 4 + r) * XROWF4 + tt * XQ + q) * 16u;
                asm volatile("cp.async.cg.shared.global [%0], [%1], 16;"
                             :: "r"(dst), "l"(g) : "memory");
            }
        }
        asm volatile("cp.async.commit_group;" ::: "memory");
    };

    issue_chunk(0, 0);
    issue_chunk(1, 1);
    asm volatile("cp.async.wait_group 1;" ::: "memory");   // chunk 0 ready
    __syncthreads();

    const int NCHUNK = T_ / CH;   // 64
    for (int c = 0; c < NCHUNK; ++c) {
        const int buf = c & 1;
        const float* Xrow = reinterpret_cast<const float*>(Xs) +
                            (size_t)(buf * 4 + s) * (XROWF4 * 4);

        #pragma unroll 2
        for (int tt = 0; tt < CH; ++tt) {
            const int p = tt & 1;          // hm read buffer (CH even, c*CH even)

            // split-K partials, 4 rows packed 2x2
            ull aZ0 = 0, aZ1 = 0, aR0 = 0, aR1 = 0, aH0 = 0, aH1 = 0;
            const ulonglong2* hz = reinterpret_cast<const ulonglong2*>(&hm[p][0][jbeg]);
            const ulonglong2* hr = reinterpret_cast<const ulonglong2*>(&hm[p][1][jbeg]);
            const ulonglong2* hh = reinterpret_cast<const ulonglong2*>(&hm[p][2][jbeg]);
            #pragma unroll
            for (int jj = 0; jj < JSEG; ++jj) {
                ulonglong2 va = hz[jj];    // .x = rows{0,1}, .y = rows{2,3}
                ulonglong2 vb = hr[jj];
                ulonglong2 vc = hh[jj];
                fma2(aZ0, va.x, Uzd[jj]); fma2(aZ1, va.y, Uzd[jj]);
                fma2(aR0, vb.x, Urd[jj]); fma2(aR1, vb.y, Urd[jj]);
                fma2(aH0, vc.x, Uhd[jj]); fma2(aH1, vc.y, Uhd[jj]);
            }
            float z0, z1, z2, z3, r0, r1, r2, r3, g0, g1, g2, g3;
            unpack2(aZ0, z0, z1); unpack2(aZ1, z2, z3);
            unpack2(aR0, r0, r1); unpack2(aR1, r2, r3);
            unpack2(aH0, g0, g1); unpack2(aH1, g2, g3);

            // butterfly over the 4 split lanes (lanes s, s^1, s^2, s^3 share u)
            #pragma unroll
            for (int d = 1; d <= 2; d <<= 1) {
                z0 += __shfl_xor_sync(0xffffffffu, z0, d);
                z1 += __shfl_xor_sync(0xffffffffu, z1, d);
                z2 += __shfl_xor_sync(0xffffffffu, z2, d);
                z3 += __shfl_xor_sync(0xffffffffu, z3, d);
                r0 += __shfl_xor_sync(0xffffffffu, r0, d);
                r1 += __shfl_xor_sync(0xffffffffu, r1, d);
                r2 += __shfl_xor_sync(0xffffffffu, r2, d);
                r3 += __shfl_xor_sync(0xffffffffu, r3, d);
                g0 += __shfl_xor_sync(0xffffffffu, g0, d);
                g1 += __shfl_xor_sync(0xffffffffu, g1, d);
                g2 += __shfl_xor_sync(0xffffffffu, g2, d);
                g3 += __shfl_xor_sync(0xffffffffu, g3, d);
            }
            // select this thread's row
            float AZ = (s == 0) ? z0 : (s == 1) ? z1 : (s == 2) ? z2 : z3;
            float AR = (s == 0) ? r0 : (s == 1) ? r1 : (s == 2) ? r2 : r3;
            float AH = (s == 0) ? g0 : (s == 1) ? g1 : (s == 2) ? g2 : g3;

            if (active) {
                const float* Xp = Xrow + tt * (XQ * 4);
                float xz = Xp[u], xr = Xp[NU + u], xh = Xp[2 * NU + u];
                float z  = sigm(xz + AZ + br0);
                float r  = sigm(xr + AR + br1);
                float th = tanh_fast(xh + r * (AH + br2));
                h = z * h + (1.f - z) * th;
                float* hb = (float*)&hm[p ^ 1][0][0];
                hb[(0 * JPAD + u) * 4 + s] = h * rdp0;   // fully coalesced
                hb[(1 * JPAD + u) * 4 + s] = h * rdp1;
                hb[(2 * JPAD + u) * 4 + s] = h * rdp2;
            }
            __syncthreads();               // the ONLY barrier per step
        }

        // chunk boundary: refill consumed buffer with chunk c+2
        if (c + 2 < NCHUNK) issue_chunk(c + 2, buf);
        asm volatile("cp.async.wait_group 1;" ::: "memory");  // chunk c+1 ready
        __syncthreads();
    }

    // dense head: out[b] = h . Wd + bd
    if (active) head[s][u] = h * wdu;
    __syncthreads();
    if (tid < 4) {
        float sum = bd[0];
        for (int uu = 0; uu < NU; ++uu) sum += head[tid][uu];
        out[b0 + tid] = sum;
    }
}

// ---------------- launch ----------------
extern "C" void kernel_launch(void* const* d_in, const int* in_sizes, int n_in,
                              void* d_out, int out_size)
{
    const float* inp = (const float*)d_in[0];
    const float* W   = (const float*)d_in[1];
    const float* U   = (const float*)d_in[2];
    const float* bb  = (const float*)d_in[3];
    const float* Wd  = (const float*)d_in[4];
    const float* bd  = (const float*)d_in[5];
    const float* dp  = (const float*)d_in[6];
    const float* rdp = (const float*)d_in[7];
    float* out = (float*)d_out;

    cudaFuncSetAttribute(xproj_kernel, cudaFuncAttributeMaxDynamicSharedMemorySize, SMEM_XPROJ);
    xproj_kernel<<<B_, 512, SMEM_XPROJ>>>(inp, W, bb, dp);
    scan_kernel<<<B_ / 4, 256>>>(U, bb, Wd, bd, rdp, out);
}